// round 1
// baseline (speedup 1.0000x reference)
#include <cuda_runtime.h>
#include <cuda_bf16.h>
#include <math.h>

// Box-embedding conditional-probability loss.
//   B pairs, D=128 dims. For each pair: gather 4 table rows, compute join/meet
//   boxes, 4 log-volumes, and pos/neg losses.
//
// Key design decision: log-volume = sum of 128 logs is replaced by
// log(product of extents). Per-dim MUFU.LG2 would cost ~470us chip-wide;
// products + bit-level mantissa/exponent split keep the hot loop on the
// FMA/ALU pipes, with only 4 accurate logf() per pair at the end.

#define EPS_F 1e-8f

static __device__ __forceinline__ float split_mant(float p, int& e) {
    int ib = __float_as_int(p);
    e = ((ib >> 23) & 0xFF) - 127;
    return __int_as_float((ib & 0x007FFFFF) | 0x3F800000);  // mantissa in [1,2)
}

__global__ void __launch_bounds__(256)
box_pair_kernel(const int* __restrict__ t1x,
                const int* __restrict__ t2x,
                const float* __restrict__ min_tab,
                const float* __restrict__ dlt_tab,
                float* __restrict__ out_pos,
                float* __restrict__ out_neg,
                int B)
{
    // Affine init-scale constants (computed in double, truncated to float,
    // matching the python-float64 -> jnp.float32 path of the reference).
    const float MIN_MEAN   = (float)((0.0001 + 0.01) / 2.0);     // 0.00505
    const float MIN_VAR    = (float)(0.01 - (0.0001 + 0.01)/2.0);// 0.00495
    const float DELTA_MEAN = (float)((0.9 + 0.999) / 2.0);       // 0.9495
    const float DELTA_VAR  = (float)(0.999 - (0.9 + 0.999)/2.0); // 0.0495

    int gtid = blockIdx.x * blockDim.x + threadIdx.x;
    int pair = gtid >> 5;
    int lane = threadIdx.x & 31;
    if (pair >= B) return;

    int i1 = t1x[pair];
    int i2 = t2x[pair];

    // Each lane owns 4 consecutive dims: one float4 per row -> fully coalesced
    // 512B warp transaction per row, 4 independent loads in flight (MLP=4).
    const float4* m1p = (const float4*)(min_tab + (size_t)i1 * 128);
    const float4* d1p = (const float4*)(dlt_tab + (size_t)i1 * 128);
    const float4* m2p = (const float4*)(min_tab + (size_t)i2 * 128);
    const float4* d2p = (const float4*)(dlt_tab + (size_t)i2 * 128);
    float4 m1 = __ldg(m1p + lane);
    float4 d1 = __ldg(d1p + lane);
    float4 m2 = __ldg(m2p + lane);
    float4 d2 = __ldg(d2p + lane);

    float p1 = 1.0f, p2 = 1.0f, pm = 1.0f, pj = 1.0f;
    float meet_raw_min = 3.4e38f;  // min over dims of raw meet extent (disjoint test)

    const float* m1v = &m1.x;
    const float* d1v = &d1.x;
    const float* m2v = &m2.x;
    const float* d2v = &d2.x;

#pragma unroll
    for (int j = 0; j < 4; j++) {
        float a  = fmaf(m1v[j], MIN_VAR, MIN_MEAN);       // t1_min
        float da = fmaf(d1v[j], DELTA_VAR, DELTA_MEAN);   // t1_delta
        float b  = a + da;                                // t1_max
        float c  = fmaf(m2v[j], MIN_VAR, MIN_MEAN);       // t2_min
        float dc = fmaf(d2v[j], DELTA_VAR, DELTA_MEAN);   // t2_delta
        float d  = c + dc;                                // t2_max

        float jmin = fminf(a, c);
        float jmax = fmaxf(b, d);
        float mmin = fmaxf(a, c);
        float mmax = fminf(b, d);

        float e1 = b - a;           // matches reference's (mn+dl)-mn rounding
        float e2 = d - c;
        float em = mmax - mmin;
        float ej = jmax - jmin;

        meet_raw_min = fminf(meet_raw_min, em);

        p1 *= fmaxf(e1, EPS_F);
        p2 *= fmaxf(e2, EPS_F);
        pm *= fmaxf(em, EPS_F);     // min 1e-32 over 4 dims: still fp32-normal
        pj *= fmaxf(ej, EPS_F);
    }

    // disjoint = any(meet_max <= meet_min)  <=>  any(em <= 0)
    bool disjoint = __any_sync(0xFFFFFFFFu, meet_raw_min <= 0.0f);

    // Split each per-lane product into mantissa [1,2) + integer exponent so
    // the cross-lane product can never under/overflow (mant prod < 2^32).
    int e1s, e2s, ems, ejs;
    float m1s = split_mant(p1, e1s);
    float m2s = split_mant(p2, e2s);
    float mms = split_mant(pm, ems);
    float mjs = split_mant(pj, ejs);

#pragma unroll
    for (int off = 16; off > 0; off >>= 1) {
        m1s *= __shfl_xor_sync(0xFFFFFFFFu, m1s, off);
        m2s *= __shfl_xor_sync(0xFFFFFFFFu, m2s, off);
        mms *= __shfl_xor_sync(0xFFFFFFFFu, mms, off);
        mjs *= __shfl_xor_sync(0xFFFFFFFFu, mjs, off);
        e1s += __shfl_xor_sync(0xFFFFFFFFu, e1s, off);
        e2s += __shfl_xor_sync(0xFFFFFFFFu, e2s, off);
        ems += __shfl_xor_sync(0xFFFFFFFFu, ems, off);
        ejs += __shfl_xor_sync(0xFFFFFFFFu, ejs, off);
    }

    if (lane == 0) {
        const float LN2 = 0.69314718055994530942f;
        float t1_log   = logf(m1s) + (float)e1s * LN2;
        float t2_log   = logf(m2s) + (float)e2s * LN2;
        float meet_log = logf(mms) + (float)ems * LN2;
        float join_log = logf(mjs) + (float)ejs * LN2;

        float cond = meet_log - t2_log;   // log P(t1|t2)

        float posv, negv;
        if (disjoint) {
            posv = join_log - t1_log;     // -(t1_log - join_log)
            negv = 0.0f;
        } else {
            posv = -cond;
            negv = -logf(fmaxf(1.0f - expf(cond), EPS_F));
        }
        out_pos[pair] = posv;
        out_neg[pair] = negv;
    }
}

extern "C" void kernel_launch(void* const* d_in, const int* in_sizes, int n_in,
                              void* d_out, int out_size) {
    const int*   t1x    = (const int*)d_in[0];
    const int*   t2x    = (const int*)d_in[1];
    const float* min_tb = (const float*)d_in[2];
    const float* dlt_tb = (const float*)d_in[3];

    int B = in_sizes[0];
    float* out_pos = (float*)d_out;          // output tuple flattened: [pos(B), neg(B)]
    float* out_neg = (float*)d_out + B;

    // 1 warp per pair, 8 warps (256 threads) per block.
    int warps_per_block = 8;
    int grid = (B + warps_per_block - 1) / warps_per_block;
    box_pair_kernel<<<grid, 256>>>(t1x, t2x, min_tb, dlt_tb, out_pos, out_neg, B);
}

// round 2
// speedup vs baseline: 1.7303x; 1.7303x over previous
#include <cuda_runtime.h>
#include <cuda_bf16.h>
#include <math.h>

// Box-embedding conditional-probability loss. B pairs, D=128.
// R2: issue-bound kernel -> minimize instruction count.
//  - 8 lanes per pair (4 pairs/warp), 16 dims/lane via 4 float4 chunks.
//  - meet_extent = e1 + e2 - join_extent (exact identity: min+max = sum),
//    removing 2 FMNMX/dim; e1,e2,ej clamps dropped (extents ~0.95 >> 1e-8).
//  - log-volume via running products; only the meet product can underflow,
//    renormalized (mantissa/exponent split) once per 4-dim chunk.
//  - 3-round butterfly reduction over 4 mantissa floats + 2 packed-exponent
//    ints (16-bit fields, bias 4096: sums over 8 lanes fit, no carries).

#define EPS_F 1e-8f

static __device__ __forceinline__ float split_mant(float p, int& e) {
    int ib = __float_as_int(p);
    e += ((ib >> 23) & 0xFF) - 127;
    return __int_as_float((ib & 0x007FFFFF) | 0x3F800000);  // [1,2)
}

__global__ void __launch_bounds__(256)
box_pair_kernel(const int* __restrict__ t1x,
                const int* __restrict__ t2x,
                const float* __restrict__ min_tab,
                const float* __restrict__ dlt_tab,
                float* __restrict__ out_pos,
                float* __restrict__ out_neg,
                int B)
{
    const float MIN_MEAN   = (float)((0.0001 + 0.01) / 2.0);
    const float MIN_VAR    = (float)(0.01 - (0.0001 + 0.01) / 2.0);
    const float DELTA_MEAN = (float)((0.9 + 0.999) / 2.0);
    const float DELTA_VAR  = (float)(0.999 - (0.9 + 0.999) / 2.0);

    int gtid = blockIdx.x * blockDim.x + threadIdx.x;
    int pair = gtid >> 3;           // 8 lanes per pair
    int sub  = threadIdx.x & 7;     // lane within group
    if (pair >= B) return;

    int i1 = __ldg(t1x + pair);
    int i2 = __ldg(t2x + pair);

    const float4* m1p = (const float4*)(min_tab + (size_t)i1 * 128) + sub;
    const float4* d1p = (const float4*)(dlt_tab + (size_t)i1 * 128) + sub;
    const float4* m2p = (const float4*)(min_tab + (size_t)i2 * 128) + sub;
    const float4* d2p = (const float4*)(dlt_tab + (size_t)i2 * 128) + sub;

    float p1 = 1.0f, p2 = 1.0f, pm = 1.0f, pj = 1.0f;
    int   E1 = 0, E2 = 0, EM = 0, EJ = 0;
    float mr = 3.4e38f;   // min over my dims of raw meet extent

#pragma unroll
    for (int c = 0; c < 4; c++) {
        float4 m1 = __ldg(m1p + c * 8);
        float4 d1 = __ldg(d1p + c * 8);
        float4 m2 = __ldg(m2p + c * 8);
        float4 d2 = __ldg(d2p + c * 8);

        const float* m1v = &m1.x;
        const float* d1v = &d1.x;
        const float* m2v = &m2.x;
        const float* d2v = &d2.x;

#pragma unroll
        for (int j = 0; j < 4; j++) {
            float a  = fmaf(m1v[j], MIN_VAR, MIN_MEAN);     // t1_min
            float da = fmaf(d1v[j], DELTA_VAR, DELTA_MEAN); // t1 extent
            float c0 = fmaf(m2v[j], MIN_VAR, MIN_MEAN);     // t2_min
            float dc = fmaf(d2v[j], DELTA_VAR, DELTA_MEAN); // t2 extent
            float b  = a + da;                              // t1_max
            float d  = c0 + dc;                             // t2_max

            float jmin = fminf(a, c0);
            float jmax = fmaxf(b, d);
            float ej   = jmax - jmin;                 // join extent
            float em   = (da + dc) - ej;              // meet extent (identity)

            mr = fminf(mr, em);
            p1 *= da;
            p2 *= dc;
            pj *= ej;
            pm *= fmaxf(em, EPS_F);
        }
        // only pm can underflow (4 dims of 1e-8 -> 1e-32); renorm per chunk
        pm = split_mant(pm, EM);
    }

    // per-lane safety split (keeps cross-lane products in fp32 range)
    p1 = split_mant(p1, E1);
    p2 = split_mant(p2, E2);
    pj = split_mant(pj, EJ);

    // pack exponents: 16-bit fields, bias 4096 (8-lane sums stay < 65536)
    unsigned pk0 = (unsigned)(E1 + 4096) | ((unsigned)(E2 + 4096) << 16);
    unsigned pk1 = (unsigned)(EM + 4096) | ((unsigned)(EJ + 4096) << 16);

    const unsigned FULL = 0xFFFFFFFFu;
#pragma unroll
    for (int off = 4; off > 0; off >>= 1) {
        p1  *= __shfl_xor_sync(FULL, p1, off);
        p2  *= __shfl_xor_sync(FULL, p2, off);
        pm  *= __shfl_xor_sync(FULL, pm, off);
        pj  *= __shfl_xor_sync(FULL, pj, off);
        pk0 += __shfl_xor_sync(FULL, pk0, off);
        pk1 += __shfl_xor_sync(FULL, pk1, off);
    }

    // disjoint = any lane in my 8-lane group saw em <= 0
    unsigned ball = __ballot_sync(FULL, mr <= 0.0f);
    bool disjoint = ((ball >> (threadIdx.x & 24)) & 0xFFu) != 0u;

    if (sub == 0) {
        const int BIAS8 = 8 * 4096;
        int e1s = (int)(pk0 & 0xFFFFu) - BIAS8;
        int e2s = (int)(pk0 >> 16)     - BIAS8;
        int ems = (int)(pk1 & 0xFFFFu) - BIAS8;
        int ejs = (int)(pk1 >> 16)     - BIAS8;

        const float LN2 = 0.69314718055994530942f;
        float t1_log   = logf(p1) + (float)e1s * LN2;
        float t2_log   = logf(p2) + (float)e2s * LN2;
        float meet_log = logf(pm) + (float)ems * LN2;
        float join_log = logf(pj) + (float)ejs * LN2;

        float cond = meet_log - t2_log;   // log P(t1|t2)

        float posv, negv;
        if (disjoint) {
            posv = join_log - t1_log;
            negv = 0.0f;
        } else {
            posv = -cond;
            negv = -logf(fmaxf(1.0f - expf(cond), EPS_F));
        }
        out_pos[pair] = posv;
        out_neg[pair] = negv;
    }
}

extern "C" void kernel_launch(void* const* d_in, const int* in_sizes, int n_in,
                              void* d_out, int out_size) {
    const int*   t1x    = (const int*)d_in[0];
    const int*   t2x    = (const int*)d_in[1];
    const float* min_tb = (const float*)d_in[2];
    const float* dlt_tb = (const float*)d_in[3];

    int B = in_sizes[0];
    float* out_pos = (float*)d_out;
    float* out_neg = (float*)d_out + B;

    // 8 lanes per pair, 32 pairs per 256-thread block
    int pairs_per_block = 32;
    int grid = (B + pairs_per_block - 1) / pairs_per_block;
    box_pair_kernel<<<grid, 256>>>(t1x, t2x, min_tb, dlt_tb, out_pos, out_neg, B);
}